// round 5
// baseline (speedup 1.0000x reference)
#include <cuda_runtime.h>

#define NB 128
#define NT 784
#define NH 256
#define NL 20
#define NC 10

__device__ float g_xp[(size_t)NB * NT * NH];
__device__ float g_y [(size_t)NB * NT * NH];

// scan smem: Ws2[64][260] + hbuf[2][256]
#define WS2_STRIDE 260
static const int SMEM_SCAN_BYTES = (64 * WS2_STRIDE + 2 * NH) * 4;

__device__ __forceinline__ void ffma2(unsigned long long &d,
                                      unsigned long long a,
                                      unsigned long long b) {
    asm("fma.rn.f32x2 %0, %1, %2, %0;" : "+l"(d) : "l"(a), "l"(b));
}
__device__ __forceinline__ unsigned long long addf2(unsigned long long a,
                                                    unsigned long long b) {
    unsigned long long r;
    asm("add.rn.f32x2 %0, %1, %2;" : "=l"(r) : "l"(a), "l"(b));
    return r;
}
__device__ __forceinline__ unsigned long long packf2(float x, float y) {
    unsigned long long r;
    asm("mov.b64 %0, {%1, %2};" : "=l"(r) : "r"(__float_as_uint(x)),
                                   "r"(__float_as_uint(y)));
    return r;
}
__device__ __forceinline__ float2 unpackf2(unsigned long long a) {
    unsigned int lo, hi;
    asm("mov.b64 {%0, %1}, %2;" : "=r"(lo), "=r"(hi) : "l"(a));
    return make_float2(__uint_as_float(lo), __uint_as_float(hi));
}

// layer-0 projection: I=1 -> xp = x*W_ih0[h] + b_ih0[h] + b_hh0[h]
__global__ void k_proj0(const float* __restrict__ x,
                        const float* __restrict__ w0,
                        const float* __restrict__ bi0,
                        const float* __restrict__ bh0) {
    int idx = blockIdx.x * 256 + threadIdx.x;
    int h  = idx & (NH - 1);
    int bt = idx >> 8;
    g_xp[idx] = x[bt] * w0[h] + bi0[h] + bh0[h];
}

// -----------------------------------------------------------------------
// Split-K recurrence. One CTA per sample. Warp w owns rows [32w, 32w+32),
// lane l owns k in {l + 32j}. 6 j-slots of weights in registers, 2 in smem.
// Cross-lane reduce-scatter leaves lane l with row 32w + l.
// -----------------------------------------------------------------------
__global__ __launch_bounds__(256, 1)
void k_scan(const float* __restrict__ Whh) {
    extern __shared__ float smem[];
    float* Ws2  = smem;                       // [64][WS2_STRIDE]
    float* hbuf = smem + 64 * WS2_STRIDE;     // [2][NH]
    const int tid = threadIdx.x;
    const int w   = tid >> 5;
    const int l   = tid & 31;
    const int b   = blockIdx.x;

    // register weights: wr[r2][j] = (W[32w+2r2][l+32j], W[32w+2r2+1][l+32j])
    unsigned long long wr[16][6];
    #pragma unroll
    for (int r2 = 0; r2 < 16; r2++) {
        const float* p0 = Whh + (size_t)(w * 32 + 2 * r2) * NH + l;
        const float* p1 = p0 + NH;
        #pragma unroll
        for (int j = 0; j < 6; j++)
            wr[r2][j] = packf2(p0[32 * j], p1[32 * j]);
    }
    // smem weights for k in [192,256): Ws2[kk][row] = W[row][192+kk]
    for (int idx = tid; idx < 64 * NH; idx += 256) {
        int row = idx >> 6, kk = idx & 63;
        Ws2[kk * WS2_STRIDE + row] = Whh[row * NH + 192 + kk];
    }
    hbuf[tid] = 0.0f; hbuf[NH + tid] = 0.0f;
    __syncthreads();

    const float* xprow = g_xp + (size_t)b * NT * NH + (w * 32 + l);
    float*       yrow  = g_y  + (size_t)b * NT * NH + (w * 32 + l);

    float xv = xprow[0];
    int cur = 0;
    for (int t = 0; t < NT; t++) {
        float xnext = (t + 1 < NT) ? xprow[(t + 1) * NH] : 0.0f;

        // coalesced h loads: lane l reads h[l + 32j]
        const float* hc = hbuf + cur * NH + l;
        float hk[8];
        #pragma unroll
        for (int j = 0; j < 8; j++) hk[j] = hc[32 * j];

        unsigned long long acc[16];
        #pragma unroll
        for (int r2 = 0; r2 < 16; r2++) acc[r2] = 0ull;

        #pragma unroll
        for (int j = 0; j < 6; j++) {
            unsigned long long hd = packf2(hk[j], hk[j]);
            #pragma unroll
            for (int r2 = 0; r2 < 16; r2++)
                ffma2(acc[r2], wr[r2][j], hd);
        }
        #pragma unroll
        for (int jj = 0; jj < 2; jj++) {
            const float* wrow = Ws2 + (l + 32 * jj) * WS2_STRIDE + w * 32;
            unsigned long long hd = packf2(hk[6 + jj], hk[6 + jj]);
            #pragma unroll
            for (int m = 0; m < 8; m++) {
                ulonglong2 wv = *(const ulonglong2*)(wrow + 4 * m);
                ffma2(acc[2 * m],     wv.x, hd);
                ffma2(acc[2 * m + 1], wv.y, hd);
            }
        }

        // butterfly reduce-scatter on packed pairs (stages 16,8,4,2)
        #pragma unroll
        for (int i = 0; i < 8; i++) {
            unsigned long long ts = (l & 16) ? acc[i] : acc[i + 8];
            unsigned long long kp = (l & 16) ? acc[i + 8] : acc[i];
            acc[i] = addf2(kp, __shfl_xor_sync(0xffffffffu, ts, 16));
        }
        #pragma unroll
        for (int i = 0; i < 4; i++) {
            unsigned long long ts = (l & 8) ? acc[i] : acc[i + 4];
            unsigned long long kp = (l & 8) ? acc[i + 4] : acc[i];
            acc[i] = addf2(kp, __shfl_xor_sync(0xffffffffu, ts, 8));
        }
        #pragma unroll
        for (int i = 0; i < 2; i++) {
            unsigned long long ts = (l & 4) ? acc[i] : acc[i + 2];
            unsigned long long kp = (l & 4) ? acc[i + 2] : acc[i];
            acc[i] = addf2(kp, __shfl_xor_sync(0xffffffffu, ts, 4));
        }
        {
            unsigned long long ts = (l & 2) ? acc[0] : acc[1];
            unsigned long long kp = (l & 2) ? acc[1] : acc[0];
            acc[0] = addf2(kp, __shfl_xor_sync(0xffffffffu, ts, 2));
        }
        // final stage: unpack pair (rows 2p, 2p+1), exchange one float
        float2 eo = unpackf2(acc[0]);
        float ts = (l & 1) ? eo.x : eo.y;
        float kp = (l & 1) ? eo.y : eo.x;
        float s  = kp + __shfl_xor_sync(0xffffffffu, ts, 1);

        float v = fmaxf(s + xv, 0.0f);
        hbuf[(cur ^ 1) * NH + w * 32 + l] = v;
        yrow[t * NH] = v;
        xv = xnext; cur ^= 1;
        __syncthreads();
    }
}

// -----------------------------------------------------------------------
// Register-tiled SGEMM projection, layers 1..L-1 (unchanged from R4).
// -----------------------------------------------------------------------
__global__ __launch_bounds__(256, 2)
void k_proj(const float* __restrict__ Wih,
            const float* __restrict__ b1,
            const float* __restrict__ b2) {
    __shared__ float As[2][16][128];
    __shared__ float Bs[2][16][128];

    const int tid = threadIdx.x;
    const int tx  = tid & 15;
    const int ty  = tid >> 4;
    const int bm  = blockIdx.x;
    const int bn  = blockIdx.y;

    const float* Ag = g_y + (size_t)bm * 128 * NH;
    const float* Bg = Wih + (size_t)bn * 128 * NH;

    const int idx0 = tid * 2;
    const int row0 = idx0 >> 2, cc0 = (idx0 & 3) * 4;
    const int idx1 = tid * 2 + 1;
    const int row1 = idx1 >> 2, cc1 = (idx1 & 3) * 4;

    #define STAGE(sel, ks)                                                  \
    {                                                                       \
        float4 a0v = *(const float4*)(Ag + row0 * NH + (ks) + cc0);         \
        float4 a1v = *(const float4*)(Ag + row1 * NH + (ks) + cc1);         \
        float4 b0v = *(const float4*)(Bg + row0 * NH + (ks) + cc0);         \
        float4 b1v = *(const float4*)(Bg + row1 * NH + (ks) + cc1);         \
        As[sel][cc0 + 0][row0] = a0v.x; As[sel][cc0 + 1][row0] = a0v.y;     \
        As[sel][cc0 + 2][row0] = a0v.z; As[sel][cc0 + 3][row0] = a0v.w;     \
        As[sel][cc1 + 0][row1] = a1v.x; As[sel][cc1 + 1][row1] = a1v.y;     \
        As[sel][cc1 + 2][row1] = a1v.z; As[sel][cc1 + 3][row1] = a1v.w;     \
        Bs[sel][cc0 + 0][row0] = b0v.x; Bs[sel][cc0 + 1][row0] = b0v.y;     \
        Bs[sel][cc0 + 2][row0] = b0v.z; Bs[sel][cc0 + 3][row0] = b0v.w;     \
        Bs[sel][cc1 + 0][row1] = b1v.x; Bs[sel][cc1 + 1][row1] = b1v.y;     \
        Bs[sel][cc1 + 2][row1] = b1v.z; Bs[sel][cc1 + 3][row1] = b1v.w;     \
    }

    unsigned long long acc[8][4];
    #pragma unroll
    for (int i = 0; i < 8; i++)
        #pragma unroll
        for (int j = 0; j < 4; j++) acc[i][j] = 0ull;

    STAGE(0, 0);
    __syncthreads();

    #pragma unroll 1
    for (int s = 0; s < 16; s++) {
        int sel = s & 1;
        if (s < 15) STAGE(sel ^ 1, (s + 1) * 16);

        #pragma unroll
        for (int k = 0; k < 16; k++) {
            float4 a0 = *(const float4*)&As[sel][k][ty * 4];
            float4 a1 = *(const float4*)&As[sel][k][64 + ty * 4];
            float4 bv0 = *(const float4*)&Bs[sel][k][tx * 4];
            float4 bv1 = *(const float4*)&Bs[sel][k][64 + tx * 4];
            unsigned long long bq0 = packf2(bv0.x, bv0.y);
            unsigned long long bq1 = packf2(bv0.z, bv0.w);
            unsigned long long bq2 = packf2(bv1.x, bv1.y);
            unsigned long long bq3 = packf2(bv1.z, bv1.w);
            float av[8] = {a0.x, a0.y, a0.z, a0.w, a1.x, a1.y, a1.z, a1.w};
            #pragma unroll
            for (int i = 0; i < 8; i++) {
                unsigned long long ad = packf2(av[i], av[i]);
                ffma2(acc[i][0], ad, bq0);
                ffma2(acc[i][1], ad, bq1);
                ffma2(acc[i][2], ad, bq2);
                ffma2(acc[i][3], ad, bq3);
            }
        }
        __syncthreads();
    }

    const int jb0 = bn * 128 + tx * 4;
    const int jb1 = jb0 + 64;
    float4 bsA, bsB;
    {
        float4 x0 = *(const float4*)(b1 + jb0);
        float4 y0 = *(const float4*)(b2 + jb0);
        bsA = make_float4(x0.x + y0.x, x0.y + y0.y, x0.z + y0.z, x0.w + y0.w);
        float4 x1 = *(const float4*)(b1 + jb1);
        float4 y1 = *(const float4*)(b2 + jb1);
        bsB = make_float4(x1.x + y1.x, x1.y + y1.y, x1.z + y1.z, x1.w + y1.w);
    }
    #pragma unroll
    for (int i = 0; i < 8; i++) {
        int row = bm * 128 + ((i < 4) ? (ty * 4 + i) : (64 + ty * 4 + i - 4));
        float* orow = g_xp + (size_t)row * NH;
        float2 p0 = unpackf2(acc[i][0]);
        float2 p1 = unpackf2(acc[i][1]);
        float2 p2 = unpackf2(acc[i][2]);
        float2 p3 = unpackf2(acc[i][3]);
        float4 o0 = make_float4(p0.x + bsA.x, p0.y + bsA.y,
                                p1.x + bsA.z, p1.y + bsA.w);
        float4 o1 = make_float4(p2.x + bsB.x, p2.y + bsB.y,
                                p3.x + bsB.z, p3.y + bsB.w);
        *(float4*)(orow + jb0) = o0;
        *(float4*)(orow + jb1) = o1;
    }
    #undef STAGE
}

__global__ void k_fc(const float* __restrict__ Wfc,
                     const float* __restrict__ bfc,
                     float* __restrict__ out) {
    int b = blockIdx.x, lane = threadIdx.x;
    const float* hrow = g_y + ((size_t)b * NT + (NT - 1)) * NH;
    float hv[8];
    #pragma unroll
    for (int k = 0; k < 8; k++) hv[k] = hrow[lane + 32 * k];
    #pragma unroll
    for (int c = 0; c < NC; c++) {
        float s = 0.0f;
        #pragma unroll
        for (int k = 0; k < 8; k++) s += hv[k] * Wfc[c * NH + lane + 32 * k];
        #pragma unroll
        for (int off = 16; off > 0; off >>= 1)
            s += __shfl_xor_sync(0xffffffffu, s, off);
        if (lane == 0) out[b * NC + c] = s + bfc[c];
    }
}

extern "C" void kernel_launch(void* const* d_in, const int* in_sizes, int n_in,
                              void* d_out, int out_size) {
    const float* x    = (const float*)d_in[0];
    const float* W0   = (const float*)d_in[1];
    const float* bi0  = (const float*)d_in[2];
    const float* Wih  = (const float*)d_in[3];
    const float* bih  = (const float*)d_in[4];
    const float* Whh  = (const float*)d_in[5];
    const float* bhh  = (const float*)d_in[6];
    const float* Wfc  = (const float*)d_in[7];
    const float* bfc  = (const float*)d_in[8];
    float* out = (float*)d_out;

    cudaFuncSetAttribute(k_scan, cudaFuncAttributeMaxDynamicSharedMemorySize,
                         SMEM_SCAN_BYTES);

    k_proj0<<<NB * NT, 256>>>(x, W0, bi0, bhh);
    dim3 pg(NT, 2);
    for (int l = 0; l < NL; l++) {
        k_scan<<<NB, 256, SMEM_SCAN_BYTES>>>(Whh + (size_t)l * NH * NH);
        if (l + 1 < NL)
            k_proj<<<pg, 256>>>(Wih + (size_t)l * NH * NH,
                                bih + (size_t)l * NH,
                                bhh + (size_t)(l + 1) * NH);
    }
    k_fc<<<NB, 32>>>(Wfc, bfc, out);
}

// round 11
// speedup vs baseline: 1.3485x; 1.3485x over previous
#include <cuda_runtime.h>
#include <cuda_bf16.h>
#include <cstdint>

#define NB 128
#define NT 784
#define NH 256
#define NL 20
#define NC 10
#define REG_K 192
#define SMEM_K 64
#define WS_STRIDE 68

__device__ float g_xp[(size_t)NB * NT * NH];
__device__ float g_y [(size_t)NB * NT * NH];
__device__ __nv_bfloat16 g_yh[(size_t)NB * NT * NH];
__device__ __nv_bfloat16 g_yl[(size_t)NB * NT * NH];
__device__ __nv_bfloat16 g_wh[(size_t)(NL - 1) * NH * NH];
__device__ __nv_bfloat16 g_wl[(size_t)(NL - 1) * NH * NH];

static const int SMEM_SCAN_BYTES = (NH * WS_STRIDE + 2 * NH) * 4;

// proj smem: 8 operand buffers (Ah,Al,Bh,Bl x 2) of 128 rows x 40 bf16 + bias
#define PSTRIDE 40                    // bf16 per row (32 data + 8 pad)
#define PROWB (PSTRIDE * 2)           // 80 bytes per row
#define POPB (128 * PROWB)            // 10240 bytes per operand buffer
#define OFF_PBIAS (8 * POPB)          // 81920
static const int SMEM_PROJ_BYTES = OFF_PBIAS + 128 * 4 + 32;

// ---------------- helpers ----------------
__device__ __forceinline__ void ffma2(unsigned long long &d,
                                      unsigned long long a,
                                      unsigned long long b) {
    asm("fma.rn.f32x2 %0, %1, %2, %0;" : "+l"(d) : "l"(a), "l"(b));
}
__device__ __forceinline__ float hsum2(unsigned long long a) {
    unsigned int lo, hi;
    asm("mov.b64 {%0, %1}, %2;" : "=r"(lo), "=r"(hi) : "l"(a));
    return __uint_as_float(lo) + __uint_as_float(hi);
}
__device__ __forceinline__ uint32_t smem_u32(const void* p) {
    uint32_t a;
    asm("{ .reg .u64 t; cvta.to.shared.u64 t, %1; cvt.u32.u64 %0, t; }"
        : "=r"(a) : "l"(p));
    return a;
}
__device__ __forceinline__ void cpasync16(uint32_t s, const void* g) {
    asm volatile("cp.async.cg.shared.global [%0], [%1], 16;"
                 :: "r"(s), "l"(g));
}
__device__ __forceinline__ void ldm_x4(uint32_t* r, uint32_t addr) {
    asm volatile("ldmatrix.sync.aligned.m8n8.x4.shared.b16 {%0,%1,%2,%3}, [%4];"
                 : "=r"(r[0]), "=r"(r[1]), "=r"(r[2]), "=r"(r[3]) : "r"(addr));
}
__device__ __forceinline__ void mma16816(float* d, const uint32_t* a,
                                         const uint32_t* b) {
    asm volatile(
        "mma.sync.aligned.m16n8k16.row.col.f32.bf16.bf16.f32 "
        "{%0,%1,%2,%3}, {%4,%5,%6,%7}, {%8,%9}, {%0,%1,%2,%3};"
        : "+f"(d[0]), "+f"(d[1]), "+f"(d[2]), "+f"(d[3])
        : "r"(a[0]), "r"(a[1]), "r"(a[2]), "r"(a[3]), "r"(b[0]), "r"(b[1]));
}

// ---------------- layer-0 projection ----------------
__global__ void k_proj0(const float* __restrict__ x,
                        const float* __restrict__ w0,
                        const float* __restrict__ bi0,
                        const float* __restrict__ bh0) {
    int idx = blockIdx.x * 256 + threadIdx.x;
    int h  = idx & (NH - 1);
    int bt = idx >> 8;
    g_xp[idx] = x[bt] * w0[h] + bi0[h] + bh0[h];
}

// ---------------- weight hi/lo split ----------------
__global__ void k_prep(const float* __restrict__ Wih) {
    int idx = blockIdx.x * 256 + threadIdx.x;
    float v = Wih[idx];
    __nv_bfloat16 h = __float2bfloat16(v);
    g_wh[idx] = h;
    g_wl[idx] = __float2bfloat16(v - __bfloat162float(h));
}

// ---------------- recurrence (R4 + bf16 hi/lo stores) ----------------
__global__ __launch_bounds__(256, 1)
void k_scan(const float* __restrict__ Whh) {
    extern __shared__ float smem[];
    float* Ws   = smem;                   // [NH][WS_STRIDE]
    float* hbuf = smem + NH * WS_STRIDE;  // [2][NH]
    const int tid = threadIdx.x;
    const int b   = blockIdx.x;

    unsigned long long wreg2[REG_K / 2];
    {
        const ulonglong2* wrow =
            reinterpret_cast<const ulonglong2*>(Whh + (size_t)tid * NH);
        #pragma unroll
        for (int j = 0; j < REG_K / 4; j++) {
            ulonglong2 v = wrow[j];
            wreg2[2 * j] = v.x; wreg2[2 * j + 1] = v.y;
        }
    }
    for (int i = tid; i < NH * SMEM_K; i += 256) {
        int row = i >> 6, col = i & (SMEM_K - 1);
        Ws[row * WS_STRIDE + col] = Whh[row * NH + REG_K + col];
    }
    hbuf[tid] = 0.0f; hbuf[NH + tid] = 0.0f;
    __syncthreads();

    const float* xprow = g_xp + (size_t)b * NT * NH + tid;
    float*       yrow  = g_y  + (size_t)b * NT * NH + tid;
    __nv_bfloat16* yhrow = g_yh + (size_t)b * NT * NH + tid;
    __nv_bfloat16* ylrow = g_yl + (size_t)b * NT * NH + tid;
    const ulonglong2* wsl =
        reinterpret_cast<const ulonglong2*>(Ws + tid * WS_STRIDE);

    float xv = xprow[0];
    int cur = 0;
    for (int t = 0; t < NT; t++) {
        float xnext = (t + 1 < NT) ? xprow[(t + 1) * NH] : 0.0f;
        const ulonglong2* hc =
            reinterpret_cast<const ulonglong2*>(hbuf + cur * NH);
        unsigned long long a0 = 0, a1 = 0, a2 = 0, a3 = 0;
        #pragma unroll
        for (int j = 0; j < REG_K / 8; j++) {
            ulonglong2 h0 = hc[2 * j];
            ffma2(a0, wreg2[4 * j + 0], h0.x);
            ffma2(a1, wreg2[4 * j + 1], h0.y);
            ulonglong2 h1 = hc[2 * j + 1];
            ffma2(a2, wreg2[4 * j + 2], h1.x);
            ffma2(a3, wreg2[4 * j + 3], h1.y);
        }
        #pragma unroll
        for (int c = 0; c < SMEM_K / 4; c++) {
            ulonglong2 wv = wsl[c];
            ulonglong2 hv = hc[REG_K / 4 + c];
            ffma2(a0, wv.x, hv.x);
            ffma2(a1, wv.y, hv.y);
        }
        float s = (hsum2(a0) + hsum2(a1)) + (hsum2(a2) + hsum2(a3));
        float v = fmaxf(s + xv, 0.0f);
        int nxt = cur ^ 1;
        hbuf[nxt * NH + tid] = v;
        yrow[t * NH] = v;
        __nv_bfloat16 vh = __float2bfloat16(v);
        yhrow[t * NH] = vh;
        ylrow[t * NH] = __float2bfloat16(v - __bfloat162float(vh));
        xv = xnext; cur = nxt;
        __syncthreads();
    }
}

// ---------------- HMMA bf16 hi/lo projection, layers 1..L-1 ----------------
// XP[128r, 128c per CTA] = Yh*Wh + Yl*Wh + Yh*Wl (fp32 acc) + bias.
// NOTE: weight pointers resolved IN DEVICE CODE from the layer index —
// passing a __device__ symbol address from host code reads the host stub
// via ATS and silently yields garbage (root cause of R8-R10 failures).
__global__ __launch_bounds__(256, 2)
void k_proj_mma(int layer,
                const float* __restrict__ b1,
                const float* __restrict__ b2) {
    extern __shared__ char psm[];
    const uint32_t sb = smem_u32(psm);
    const int tid  = threadIdx.x;
    const int wid  = tid >> 5;
    const int lane = tid & 31;
    const int bm   = blockIdx.x;
    const int bn   = blockIdx.y;

    const int wm = (wid >> 1) * 32;   // warp m offset (0,32,64,96)
    const int wn = (wid & 1) * 64;    // warp n offset (0,64)

    const __nv_bfloat16* Wh_ = g_wh + (size_t)layer * NH * NH;
    const __nv_bfloat16* Wl_ = g_wl + (size_t)layer * NH * NH;

    const __nv_bfloat16* srcA_h = g_yh + (size_t)bm * 128 * NH;
    const __nv_bfloat16* srcA_l = g_yl + (size_t)bm * 128 * NH;
    const __nv_bfloat16* srcB_h = Wh_ + (size_t)bn * 128 * NH;
    const __nv_bfloat16* srcB_l = Wl_ + (size_t)bn * 128 * NH;

    float* sbias = (float*)(psm + OFF_PBIAS);
    if (tid < 128)
        sbias[tid] = b1[bn * 128 + tid] + b2[bn * 128 + tid];

    const int srow0 = (tid * 2) >> 2,     ssl0 = (tid * 2) & 3;
    const int srow1 = (tid * 2 + 1) >> 2, ssl1 = (tid * 2 + 1) & 3;

    #define PSTAGE(c, bsel)                                                   \
    {                                                                         \
        int kc = (c) * 32;                                                    \
        const __nv_bfloat16* gs[4] = {srcA_h, srcA_l, srcB_h, srcB_l};        \
        _Pragma("unroll")                                                     \
        for (int op = 0; op < 4; op++) {                                      \
            uint32_t base = sb + (uint32_t)(op * 2 + (bsel)) * POPB;          \
            cpasync16(base + srow0 * PROWB + ssl0 * 16,                       \
                      gs[op] + (size_t)srow0 * NH + kc + ssl0 * 8);           \
            cpasync16(base + srow1 * PROWB + ssl1 * 16,                       \
                      gs[op] + (size_t)srow1 * NH + kc + ssl1 * 8);           \
        }                                                                     \
    }

    float acc[2][8][4];
    #pragma unroll
    for (int mt = 0; mt < 2; mt++)
        #pragma unroll
        for (int nt = 0; nt < 8; nt++)
            #pragma unroll
            for (int i = 0; i < 4; i++) acc[mt][nt][i] = 0.0f;

    const int laneRowA = lane & 15;
    const int laneColA = (lane >> 4) * 8;
    const int laneRowB = (lane & 7) + ((lane >> 4) * 8);
    const int laneColB = ((lane >> 3) & 1) * 8;

    PSTAGE(0, 0);
    asm volatile("cp.async.commit_group;");
    asm volatile("cp.async.wait_group 0;");
    __syncthreads();

    #pragma unroll 1
    for (int c = 0; c < 8; c++) {
        int sel = c & 1;
        if (c < 7) {
            PSTAGE(c + 1, sel ^ 1);
            asm volatile("cp.async.commit_group;");
        }
        uint32_t aH = sb + (uint32_t)(0 * 2 + sel) * POPB;
        uint32_t aL = sb + (uint32_t)(1 * 2 + sel) * POPB;
        uint32_t bH = sb + (uint32_t)(2 * 2 + sel) * POPB;
        uint32_t bL = sb + (uint32_t)(3 * 2 + sel) * POPB;

        #pragma unroll
        for (int kk = 0; kk < 32; kk += 16) {
            uint32_t ah[2][4], bb[4][4], al[2][4];
            #pragma unroll
            for (int mt = 0; mt < 2; mt++)
                ldm_x4(ah[mt], aH + (wm + mt * 16 + laneRowA) * PROWB
                               + (kk + laneColA) * 2);
            #pragma unroll
            for (int nb = 0; nb < 4; nb++)
                ldm_x4(bb[nb], bH + (wn + nb * 16 + laneRowB) * PROWB
                               + (kk + laneColB) * 2);
            #pragma unroll
            for (int mt = 0; mt < 2; mt++)
                #pragma unroll
                for (int nt = 0; nt < 8; nt++)
                    mma16816(acc[mt][nt], ah[mt], &bb[nt >> 1][(nt & 1) * 2]);
            // Yl * Wh
            #pragma unroll
            for (int mt = 0; mt < 2; mt++)
                ldm_x4(al[mt], aL + (wm + mt * 16 + laneRowA) * PROWB
                               + (kk + laneColA) * 2);
            #pragma unroll
            for (int mt = 0; mt < 2; mt++)
                #pragma unroll
                for (int nt = 0; nt < 8; nt++)
                    mma16816(acc[mt][nt], al[mt], &bb[nt >> 1][(nt & 1) * 2]);
            // Yh * Wl (reuse bb regs)
            #pragma unroll
            for (int nb = 0; nb < 4; nb++)
                ldm_x4(bb[nb], bL + (wn + nb * 16 + laneRowB) * PROWB
                               + (kk + laneColB) * 2);
            #pragma unroll
            for (int mt = 0; mt < 2; mt++)
                #pragma unroll
                for (int nt = 0; nt < 8; nt++)
                    mma16816(acc[mt][nt], ah[mt], &bb[nt >> 1][(nt & 1) * 2]);
        }
        if (c < 7) asm volatile("cp.async.wait_group 0;");
        __syncthreads();
    }

    // epilogue: c0,c1 -> (row l/4, col 2(l%4)); c2,c3 -> row +8
    const int rl = lane >> 2;
    const int cl = 2 * (lane & 3);
    #pragma unroll
    for (int mt = 0; mt < 2; mt++) {
        #pragma unroll
        for (int nt = 0; nt < 8; nt++) {
            int gr = bm * 128 + wm + mt * 16 + rl;
            int lc = wn + nt * 8 + cl;
            int gc = bn * 128 + lc;
            float bx = sbias[lc], by = sbias[lc + 1];
            float2 o0 = make_float2(acc[mt][nt][0] + bx, acc[mt][nt][1] + by);
            float2 o1 = make_float2(acc[mt][nt][2] + bx, acc[mt][nt][3] + by);
            *(float2*)(g_xp + (size_t)gr * NH + gc) = o0;
            *(float2*)(g_xp + (size_t)(gr + 8) * NH + gc) = o1;
        }
    }
    #undef PSTAGE
}

// ---------------- final FC ----------------
__global__ void k_fc(const float* __restrict__ Wfc,
                     const float* __restrict__ bfc,
                     float* __restrict__ out) {
    int b = blockIdx.x, lane = threadIdx.x;
    const float* hrow = g_y + ((size_t)b * NT + (NT - 1)) * NH;
    float hv[8];
    #pragma unroll
    for (int k = 0; k < 8; k++) hv[k] = hrow[lane + 32 * k];
    #pragma unroll
    for (int c = 0; c < NC; c++) {
        float s = 0.0f;
        #pragma unroll
        for (int k = 0; k < 8; k++) s += hv[k] * Wfc[c * NH + lane + 32 * k];
        #pragma unroll
        for (int off = 16; off > 0; off >>= 1)
            s += __shfl_xor_sync(0xffffffffu, s, off);
        if (lane == 0) out[b * NC + c] = s + bfc[c];
    }
}

extern "C" void kernel_launch(void* const* d_in, const int* in_sizes, int n_in,
                              void* d_out, int out_size) {
    const float* x    = (const float*)d_in[0];
    const float* W0   = (const float*)d_in[1];
    const float* bi0  = (const float*)d_in[2];
    const float* Wih  = (const float*)d_in[3];
    const float* bih  = (const float*)d_in[4];
    const float* Whh  = (const float*)d_in[5];
    const float* bhh  = (const float*)d_in[6];
    const float* Wfc  = (const float*)d_in[7];
    const float* bfc  = (const float*)d_in[8];
    float* out = (float*)d_out;

    cudaFuncSetAttribute(k_scan, cudaFuncAttributeMaxDynamicSharedMemorySize,
                         SMEM_SCAN_BYTES);
    cudaFuncSetAttribute(k_proj_mma,
                         cudaFuncAttributeMaxDynamicSharedMemorySize,
                         SMEM_PROJ_BYTES);

    k_prep<<<(NL - 1) * NH * NH / 256, 256>>>(Wih);
    k_proj0<<<NB * NT, 256>>>(x, W0, bi0, bhh);
    dim3 pg(NT, 2);
    for (int l = 0; l < NL; l++) {
        k_scan<<<NB, 256, SMEM_SCAN_BYTES>>>(Whh + (size_t)l * NH * NH);
        if (l + 1 < NL)
            k_proj_mma<<<pg, 256, SMEM_PROJ_BYTES>>>(
                l,
                bih + (size_t)l * NH,
                bhh + (size_t)(l + 1) * NH);
    }
    k_fc<<<NB, 32>>>(Wfc, bfc, out);
}

// round 13
// speedup vs baseline: 1.4061x; 1.0427x over previous
#include <cuda_runtime.h>
#include <cuda_bf16.h>
#include <cstdint>

#define NB 128
#define NT 784
#define NH 256
#define NL 20
#define NC 10
#define REG_K 192
#define SMEM_K 64
#define WS_STRIDE 68

__device__ float g_xp[(size_t)NB * NT * NH];
__device__ float g_y [(size_t)NB * NT * NH];
__device__ __nv_bfloat16 g_yh[(size_t)NB * NT * NH];
__device__ __nv_bfloat16 g_yl[(size_t)NB * NT * NH];
__device__ __nv_bfloat16 g_wh[(size_t)(NL - 1) * NH * NH];
__device__ __nv_bfloat16 g_wl[(size_t)(NL - 1) * NH * NH];

static const int SMEM_SCAN_BYTES = (NH * WS_STRIDE + 2 * NH) * 4;

// proj smem: 8 operand buffers (Ah,Al,Bh,Bl x 2) of 128 rows x 40 bf16 + bias
#define PSTRIDE 40                    // bf16 per row (32 data + 8 pad)
#define PROWB (PSTRIDE * 2)           // 80 bytes per row
#define POPB (128 * PROWB)            // 10240 bytes per operand buffer
#define OFF_PBIAS (8 * POPB)          // 81920
static const int SMEM_PROJ_BYTES = OFF_PBIAS + 128 * 4 + 32;

// ---------------- helpers ----------------
__device__ __forceinline__ void ffma2(unsigned long long &d,
                                      unsigned long long a,
                                      unsigned long long b) {
    asm("fma.rn.f32x2 %0, %1, %2, %0;" : "+l"(d) : "l"(a), "l"(b));
}
__device__ __forceinline__ float hsum2(unsigned long long a) {
    unsigned int lo, hi;
    asm("mov.b64 {%0, %1}, %2;" : "=r"(lo), "=r"(hi) : "l"(a));
    return __uint_as_float(lo) + __uint_as_float(hi);
}
__device__ __forceinline__ uint32_t smem_u32(const void* p) {
    uint32_t a;
    asm("{ .reg .u64 t; cvta.to.shared.u64 t, %1; cvt.u32.u64 %0, t; }"
        : "=r"(a) : "l"(p));
    return a;
}
__device__ __forceinline__ void cpasync16(uint32_t s, const void* g) {
    asm volatile("cp.async.cg.shared.global [%0], [%1], 16;"
                 :: "r"(s), "l"(g));
}
__device__ __forceinline__ void ldm_x4(uint32_t* r, uint32_t addr) {
    asm volatile("ldmatrix.sync.aligned.m8n8.x4.shared.b16 {%0,%1,%2,%3}, [%4];"
                 : "=r"(r[0]), "=r"(r[1]), "=r"(r[2]), "=r"(r[3]) : "r"(addr));
}
__device__ __forceinline__ void mma16816(float* d, const uint32_t* a,
                                         const uint32_t* b) {
    asm volatile(
        "mma.sync.aligned.m16n8k16.row.col.f32.bf16.bf16.f32 "
        "{%0,%1,%2,%3}, {%4,%5,%6,%7}, {%8,%9}, {%0,%1,%2,%3};"
        : "+f"(d[0]), "+f"(d[1]), "+f"(d[2]), "+f"(d[3])
        : "r"(a[0]), "r"(a[1]), "r"(a[2]), "r"(a[3]), "r"(b[0]), "r"(b[1]));
}

// ---------------- layer-0 projection ----------------
__global__ void k_proj0(const float* __restrict__ x,
                        const float* __restrict__ w0,
                        const float* __restrict__ bi0,
                        const float* __restrict__ bh0) {
    int idx = blockIdx.x * 256 + threadIdx.x;
    int h  = idx & (NH - 1);
    int bt = idx >> 8;
    g_xp[idx] = x[bt] * w0[h] + bi0[h] + bh0[h];
}

// ---------------- weight hi/lo split ----------------
__global__ void k_prep(const float* __restrict__ Wih) {
    int idx = blockIdx.x * 256 + threadIdx.x;
    float v = Wih[idx];
    __nv_bfloat16 h = __float2bfloat16(v);
    g_wh[idx] = h;
    g_wl[idx] = __float2bfloat16(v - __bfloat162float(h));
}

// ---------------- recurrence (R4 + bf16 hi/lo stores) ----------------
__global__ __launch_bounds__(256, 1)
void k_scan(const float* __restrict__ Whh) {
    extern __shared__ float smem[];
    float* Ws   = smem;                   // [NH][WS_STRIDE]
    float* hbuf = smem + NH * WS_STRIDE;  // [2][NH]
    const int tid = threadIdx.x;
    const int b   = blockIdx.x;

    unsigned long long wreg2[REG_K / 2];
    {
        const ulonglong2* wrow =
            reinterpret_cast<const ulonglong2*>(Whh + (size_t)tid * NH);
        #pragma unroll
        for (int j = 0; j < REG_K / 4; j++) {
            ulonglong2 v = wrow[j];
            wreg2[2 * j] = v.x; wreg2[2 * j + 1] = v.y;
        }
    }
    for (int i = tid; i < NH * SMEM_K; i += 256) {
        int row = i >> 6, col = i & (SMEM_K - 1);
        Ws[row * WS_STRIDE + col] = Whh[row * NH + REG_K + col];
    }
    hbuf[tid] = 0.0f; hbuf[NH + tid] = 0.0f;
    __syncthreads();

    const float* xprow = g_xp + (size_t)b * NT * NH + tid;
    float*       yrow  = g_y  + (size_t)b * NT * NH + tid;
    __nv_bfloat16* yhrow = g_yh + (size_t)b * NT * NH + tid;
    __nv_bfloat16* ylrow = g_yl + (size_t)b * NT * NH + tid;
    const ulonglong2* wsl =
        reinterpret_cast<const ulonglong2*>(Ws + tid * WS_STRIDE);

    float xv = xprow[0];
    int cur = 0;
    for (int t = 0; t < NT; t++) {
        float xnext = (t + 1 < NT) ? xprow[(t + 1) * NH] : 0.0f;
        const ulonglong2* hc =
            reinterpret_cast<const ulonglong2*>(hbuf + cur * NH);
        unsigned long long a0 = 0, a1 = 0, a2 = 0, a3 = 0;
        #pragma unroll
        for (int j = 0; j < REG_K / 8; j++) {
            ulonglong2 h0 = hc[2 * j];
            ffma2(a0, wreg2[4 * j + 0], h0.x);
            ffma2(a1, wreg2[4 * j + 1], h0.y);
            ulonglong2 h1 = hc[2 * j + 1];
            ffma2(a2, wreg2[4 * j + 2], h1.x);
            ffma2(a3, wreg2[4 * j + 3], h1.y);
        }
        #pragma unroll
        for (int c = 0; c < SMEM_K / 4; c++) {
            ulonglong2 wv = wsl[c];
            ulonglong2 hv = hc[REG_K / 4 + c];
            ffma2(a0, wv.x, hv.x);
            ffma2(a1, wv.y, hv.y);
        }
        float s = (hsum2(a0) + hsum2(a1)) + (hsum2(a2) + hsum2(a3));
        float v = fmaxf(s + xv, 0.0f);
        int nxt = cur ^ 1;
        hbuf[nxt * NH + tid] = v;
        yrow[t * NH] = v;
        __nv_bfloat16 vh = __float2bfloat16(v);
        yhrow[t * NH] = vh;
        ylrow[t * NH] = __float2bfloat16(v - __bfloat162float(vh));
        xv = xnext; cur = nxt;
        __syncthreads();
    }
}

// ---------------- HMMA bf16 hi/lo projection, layers 1..L-1 ----------------
// XP[128r, 128c per CTA] = Yh*Wh + Yl*Wh + Yh*Wl (fp32 acc) + bias.
// NOTE: weight pointers resolved IN DEVICE CODE from the layer index —
// passing a __device__ symbol address from host code reads the host stub
// via ATS and silently yields garbage (root cause of R8-R10 failures).
__global__ __launch_bounds__(256, 2)
void k_proj_mma(int layer,
                const float* __restrict__ b1,
                const float* __restrict__ b2) {
    extern __shared__ char psm[];
    const uint32_t sb = smem_u32(psm);
    const int tid  = threadIdx.x;
    const int wid  = tid >> 5;
    const int lane = tid & 31;
    const int bm   = blockIdx.x;
    const int bn   = blockIdx.y;

    const int wm = (wid >> 1) * 32;   // warp m offset (0,32,64,96)
    const int wn = (wid & 1) * 64;    // warp n offset (0,64)

    const __nv_bfloat16* Wh_ = g_wh + (size_t)layer * NH * NH;
    const __nv_bfloat16* Wl_ = g_wl + (size_t)layer * NH * NH;

    const __nv_bfloat16* srcA_h = g_yh + (size_t)bm * 128 * NH;
    const __nv_bfloat16* srcA_l = g_yl + (size_t)bm * 128 * NH;
    const __nv_bfloat16* srcB_h = Wh_ + (size_t)bn * 128 * NH;
    const __nv_bfloat16* srcB_l = Wl_ + (size_t)bn * 128 * NH;

    float* sbias = (float*)(psm + OFF_PBIAS);
    if (tid < 128)
        sbias[tid] = b1[bn * 128 + tid] + b2[bn * 128 + tid];

    const int srow0 = (tid * 2) >> 2,     ssl0 = (tid * 2) & 3;
    const int srow1 = (tid * 2 + 1) >> 2, ssl1 = (tid * 2 + 1) & 3;

    #define PSTAGE(c, bsel)                                                   \
    {                                                                         \
        int kc = (c) * 32;                                                    \
        const __nv_bfloat16* gs[4] = {srcA_h, srcA_l, srcB_h, srcB_l};        \
        _Pragma("unroll")                                                     \
        for (int op = 0; op < 4; op++) {                                      \
            uint32_t base = sb + (uint32_t)(op * 2 + (bsel)) * POPB;          \
            cpasync16(base + srow0 * PROWB + ssl0 * 16,                       \
                      gs[op] + (size_t)srow0 * NH + kc + ssl0 * 8);           \
            cpasync16(base + srow1 * PROWB + ssl1 * 16,                       \
                      gs[op] + (size_t)srow1 * NH + kc + ssl1 * 8);           \
        }                                                                     \
    }

    float acc[2][8][4];
    #pragma unroll
    for (int mt = 0; mt < 2; mt++)
        #pragma unroll
        for (int nt = 0; nt < 8; nt++)
            #pragma unroll
            for (int i = 0; i < 4; i++) acc[mt][nt][i] = 0.0f;

    const int laneRowA = lane & 15;
    const int laneColA = (lane >> 4) * 8;
    const int laneRowB = (lane & 7) + ((lane >> 4) * 8);
    const int laneColB = ((lane >> 3) & 1) * 8;

    PSTAGE(0, 0);
    asm volatile("cp.async.commit_group;");
    asm volatile("cp.async.wait_group 0;");
    __syncthreads();

    #pragma unroll 1
    for (int c = 0; c < 8; c++) {
        int sel = c & 1;
        if (c < 7) {
            PSTAGE(c + 1, sel ^ 1);
            asm volatile("cp.async.commit_group;");
        }
        uint32_t aH = sb + (uint32_t)(0 * 2 + sel) * POPB;
        uint32_t aL = sb + (uint32_t)(1 * 2 + sel) * POPB;
        uint32_t bH = sb + (uint32_t)(2 * 2 + sel) * POPB;
        uint32_t bL = sb + (uint32_t)(3 * 2 + sel) * POPB;

        #pragma unroll
        for (int kk = 0; kk < 32; kk += 16) {
            uint32_t ah[2][4], bb[4][4], al[2][4];
            #pragma unroll
            for (int mt = 0; mt < 2; mt++)
                ldm_x4(ah[mt], aH + (wm + mt * 16 + laneRowA) * PROWB
                               + (kk + laneColA) * 2);
            #pragma unroll
            for (int nb = 0; nb < 4; nb++)
                ldm_x4(bb[nb], bH + (wn + nb * 16 + laneRowB) * PROWB
                               + (kk + laneColB) * 2);
            #pragma unroll
            for (int mt = 0; mt < 2; mt++)
                #pragma unroll
                for (int nt = 0; nt < 8; nt++)
                    mma16816(acc[mt][nt], ah[mt], &bb[nt >> 1][(nt & 1) * 2]);
            // Yl * Wh
            #pragma unroll
            for (int mt = 0; mt < 2; mt++)
                ldm_x4(al[mt], aL + (wm + mt * 16 + laneRowA) * PROWB
                               + (kk + laneColA) * 2);
            #pragma unroll
            for (int mt = 0; mt < 2; mt++)
                #pragma unroll
                for (int nt = 0; nt < 8; nt++)
                    mma16816(acc[mt][nt], al[mt], &bb[nt >> 1][(nt & 1) * 2]);
            // Yh * Wl (reuse bb regs)
            #pragma unroll
            for (int nb = 0; nb < 4; nb++)
                ldm_x4(bb[nb], bL + (wn + nb * 16 + laneRowB) * PROWB
                               + (kk + laneColB) * 2);
            #pragma unroll
            for (int mt = 0; mt < 2; mt++)
                #pragma unroll
                for (int nt = 0; nt < 8; nt++)
                    mma16816(acc[mt][nt], ah[mt], &bb[nt >> 1][(nt & 1) * 2]);
        }
        if (c < 7) asm volatile("cp.async.wait_group 0;");
        __syncthreads();
    }

    // epilogue: c0,c1 -> (row l/4, col 2(l%4)); c2,c3 -> row +8
    const int rl = lane >> 2;
    const int cl = 2 * (lane & 3);
    #pragma unroll
    for (int mt = 0; mt < 2; mt++) {
        #pragma unroll
        for (int nt = 0; nt < 8; nt++) {
            int gr = bm * 128 + wm + mt * 16 + rl;
            int lc = wn + nt * 8 + cl;
            int gc = bn * 128 + lc;
            float bx = sbias[lc], by = sbias[lc + 1];
            float2 o0 = make_float2(acc[mt][nt][0] + bx, acc[mt][nt][1] + by);
            float2 o1 = make_float2(acc[mt][nt][2] + bx, acc[mt][nt][3] + by);
            *(float2*)(g_xp + (size_t)gr * NH + gc) = o0;
            *(float2*)(g_xp + (size_t)(gr + 8) * NH + gc) = o1;
        }
    }
    #undef PSTAGE
}

// ---------------- final FC ----------------
__global__ void k_fc(const float* __restrict__ Wfc,
                     const float* __restrict__ bfc,
                     float* __restrict__ out) {
    int b = blockIdx.x, lane = threadIdx.x;
    const float* hrow = g_y + ((size_t)b * NT + (NT - 1)) * NH;
    float hv[8];
    #pragma unroll
    for (int k = 0; k < 8; k++) hv[k] = hrow[lane + 32 * k];
    #pragma unroll
    for (int c = 0; c < NC; c++) {
        float s = 0.0f;
        #pragma unroll
        for (int k = 0; k < 8; k++) s += hv[k] * Wfc[c * NH + lane + 32 * k];
        #pragma unroll
        for (int off = 16; off > 0; off >>= 1)
            s += __shfl_xor_sync(0xffffffffu, s, off);
        if (lane == 0) out[b * NC + c] = s + bfc[c];
    }
}

extern "C" void kernel_launch(void* const* d_in, const int* in_sizes, int n_in,
                              void* d_out, int out_size) {
    const float* x    = (const float*)d_in[0];
    const float* W0   = (const float*)d_in[1];
    const float* bi0  = (const float*)d_in[2];
    const float* Wih  = (const float*)d_in[3];
    const float* bih  = (const float*)d_in[4];
    const float* Whh  = (const float*)d_in[5];
    const float* bhh  = (const float*)d_in[6];
    const float* Wfc  = (const float*)d_in[7];
    const float* bfc  = (const float*)d_in[8];
    float* out = (float*)d_out;

    cudaFuncSetAttribute(k_scan, cudaFuncAttributeMaxDynamicSharedMemorySize,
                         SMEM_SCAN_BYTES);
    cudaFuncSetAttribute(k_proj_mma,
                         cudaFuncAttributeMaxDynamicSharedMemorySize,
                         SMEM_PROJ_BYTES);

    k_prep<<<(NL - 1) * NH * NH / 256, 256>>>(Wih);
    k_proj0<<<NB * NT, 256>>>(x, W0, bi0, bhh);
    dim3 pg(NT, 2);
    for (int l = 0; l < NL; l++) {
        k_scan<<<NB, 256, SMEM_SCAN_BYTES>>>(Whh + (size_t)l * NH * NH);
        if (l + 1 < NL)
            k_proj_mma<<<pg, 256, SMEM_PROJ_BYTES>>>(
                l,
                bih + (size_t)l * NH,
                bhh + (size_t)(l + 1) * NH);
    }
    k_fc<<<NB, 32>>>(Wfc, bfc, out);
}

// round 15
// speedup vs baseline: 1.5321x; 1.0897x over previous
#include <cuda_runtime.h>
#include <cuda_bf16.h>
#include <cstdint>

#define NB 128
#define NT 784
#define NH 256
#define NL 20
#define NC 10

__device__ float g_xp[(size_t)NB * NT * NH];
__device__ float g_y [(size_t)NB * NT * NH];
__device__ __nv_bfloat16 g_yh[(size_t)NB * NT * NH];
__device__ __nv_bfloat16 g_yl[(size_t)NB * NT * NH];
__device__ __nv_bfloat16 g_wh[(size_t)(NL - 1) * NH * NH];
__device__ __nv_bfloat16 g_wl[(size_t)(NL - 1) * NH * NH];

// scan smem: Wsm pairs 64KB + partials 8KB + hbuf 2KB
#define OFF_WSM  0
#define OFF_PART 65536
#define OFF_HBUF (65536 + 8192)
static const int SMEM_SCAN_BYTES = 65536 + 8192 + 2048;

// proj smem: 8 operand buffers (Ah,Al,Bh,Bl x 2) of 128 rows x 40 bf16 + bias
#define PSTRIDE 40
#define PROWB (PSTRIDE * 2)
#define POPB (128 * PROWB)
#define OFF_PBIAS (8 * POPB)
static const int SMEM_PROJ_BYTES = OFF_PBIAS + 128 * 4 + 32;

// ---------------- helpers ----------------
__device__ __forceinline__ void ffma2(unsigned long long &d,
                                      unsigned long long a,
                                      unsigned long long b) {
    asm("fma.rn.f32x2 %0, %1, %2, %0;" : "+l"(d) : "l"(a), "l"(b));
}
__device__ __forceinline__ float hsum2(unsigned long long a) {
    unsigned int lo, hi;
    asm("mov.b64 {%0, %1}, %2;" : "=r"(lo), "=r"(hi) : "l"(a));
    return __uint_as_float(lo) + __uint_as_float(hi);
}
__device__ __forceinline__ uint32_t smem_u32(const void* p) {
    uint32_t a;
    asm("{ .reg .u64 t; cvta.to.shared.u64 t, %1; cvt.u32.u64 %0, t; }"
        : "=r"(a) : "l"(p));
    return a;
}
__device__ __forceinline__ void cpasync16(uint32_t s, const void* g) {
    asm volatile("cp.async.cg.shared.global [%0], [%1], 16;"
                 :: "r"(s), "l"(g));
}
__device__ __forceinline__ void ldm_x4(uint32_t* r, uint32_t addr) {
    asm volatile("ldmatrix.sync.aligned.m8n8.x4.shared.b16 {%0,%1,%2,%3}, [%4];"
                 : "=r"(r[0]), "=r"(r[1]), "=r"(r[2]), "=r"(r[3]) : "r"(addr));
}
__device__ __forceinline__ void mma16816(float* d, const uint32_t* a,
                                         const uint32_t* b) {
    asm volatile(
        "mma.sync.aligned.m16n8k16.row.col.f32.bf16.bf16.f32 "
        "{%0,%1,%2,%3}, {%4,%5,%6,%7}, {%8,%9}, {%0,%1,%2,%3};"
        : "+f"(d[0]), "+f"(d[1]), "+f"(d[2]), "+f"(d[3])
        : "r"(a[0]), "r"(a[1]), "r"(a[2]), "r"(a[3]), "r"(b[0]), "r"(b[1]));
}

// ---------------- layer-0 projection ----------------
__global__ void k_proj0(const float* __restrict__ x,
                        const float* __restrict__ w0,
                        const float* __restrict__ bi0,
                        const float* __restrict__ bh0) {
    int idx = blockIdx.x * 256 + threadIdx.x;
    int h  = idx & (NH - 1);
    int bt = idx >> 8;
    g_xp[idx] = x[bt] * w0[h] + bi0[h] + bh0[h];
}

// ---------------- weight hi/lo split ----------------
__global__ void k_prep(const float* __restrict__ Wih) {
    int idx = blockIdx.x * 256 + threadIdx.x;
    float v = Wih[idx];
    __nv_bfloat16 h = __float2bfloat16(v);
    g_wh[idx] = h;
    g_wl[idx] = __float2bfloat16(v - __bfloat162float(h));
}

// ---------------- K-split recurrence with smem reduction ----------------
// Warp w owns k in [32w, 32w+32); lane l owns rows {l+32j}.
// Per thread: 8 rows x (12 reg-pairs + 4 smem-pairs) = 256 weights.
// Reduction: part[w][r] summed by thread r.
__global__ __launch_bounds__(256, 1)
void k_scan(const float* __restrict__ Whh) {
    extern __shared__ char smem[];
    unsigned long long* Wsm = (unsigned long long*)(smem + OFF_WSM); // [32][256]
    float* part = (float*)(smem + OFF_PART);                          // [8][256]
    float* hbuf = (float*)(smem + OFF_HBUF);                          // [2][256]
    const int tid = threadIdx.x;
    const int w   = tid >> 5;
    const int l   = tid & 31;
    const int b   = blockIdx.x;

    // RF weights: wr[j][p] = (W[l+32j][32w+2p], W[l+32j][32w+2p+1]), p<12
    unsigned long long wr[8][12];
    #pragma unroll
    for (int j = 0; j < 8; j++) {
        const unsigned long long* row =
            (const unsigned long long*)(Whh + (size_t)(l + 32 * j) * NH + 32 * w);
        #pragma unroll
        for (int p = 0; p < 12; p++) wr[j][p] = row[p];
    }
    // smem weights (pairs), k in [32w+24, 32w+32): Wsm[w*4+pp][r]
    for (int idx = tid; idx < 32 * 256; idx += 256) {
        int r  = idx & 255;
        int wp = idx >> 8;            // 0..31
        int ww = wp >> 2, pp = wp & 3;
        Wsm[idx] = *(const unsigned long long*)
            (Whh + (size_t)r * NH + 32 * ww + 24 + 2 * pp);
    }
    hbuf[tid] = 0.0f; hbuf[NH + tid] = 0.0f;
    __syncthreads();

    const float* xprow = g_xp + (size_t)b * NT * NH + tid;
    float*       yrow  = g_y  + (size_t)b * NT * NH + tid;
    __nv_bfloat16* yhrow = g_yh + (size_t)b * NT * NH + tid;
    __nv_bfloat16* ylrow = g_yl + (size_t)b * NT * NH + tid;

    float xv = xprow[0];
    int cur = 0;
    for (int t = 0; t < NT; t++) {
        float xnext = (t + 1 < NT) ? xprow[(t + 1) * NH] : 0.0f;

        unsigned long long acc[8];
        #pragma unroll
        for (int j = 0; j < 8; j++) acc[j] = 0ull;

        // h pairs for this warp's k-slice (uniform loads), chunked 2 LDS.128
        const ulonglong2* hcp =
            (const ulonglong2*)(hbuf + cur * NH + 32 * w);
        #pragma unroll
        for (int c = 0; c < 3; c++) {           // 3 chunks x 4 pairs (RF part)
            ulonglong2 h0 = hcp[2 * c];
            ulonglong2 h1 = hcp[2 * c + 1];
            unsigned long long hp[4] = {h0.x, h0.y, h1.x, h1.y};
            #pragma unroll
            for (int q = 0; q < 4; q++) {
                #pragma unroll
                for (int j = 0; j < 8; j++)
                    ffma2(acc[j], wr[j][4 * c + q], hp[q]);
            }
        }
        {   // smem-weight part: pairs 12..15
            ulonglong2 h0 = hcp[6];
            ulonglong2 h1 = hcp[7];
            unsigned long long hp[4] = {h0.x, h0.y, h1.x, h1.y};
            #pragma unroll
            for (int q = 0; q < 4; q++) {
                const unsigned long long* wrow = Wsm + (w * 4 + q) * 256 + l;
                #pragma unroll
                for (int j = 0; j < 8; j++)
                    ffma2(acc[j], wrow[32 * j], hp[q]);
            }
        }
        // partials
        #pragma unroll
        for (int j = 0; j < 8; j++)
            part[w * 256 + l + 32 * j] = hsum2(acc[j]);
        __syncthreads();

        // reduce row tid across 8 warps
        float s = 0.0f;
        #pragma unroll
        for (int ww = 0; ww < 8; ww++) s += part[ww * 256 + tid];
        float v = fmaxf(s + xv, 0.0f);
        int nxt = cur ^ 1;
        hbuf[nxt * NH + tid] = v;
        yrow[t * NH] = v;
        __nv_bfloat16 vh = __float2bfloat16(v);
        yhrow[t * NH] = vh;
        ylrow[t * NH] = __float2bfloat16(v - __bfloat162float(vh));
        xv = xnext; cur = nxt;
        __syncthreads();
    }
}

// ---------------- HMMA bf16 hi/lo projection (R13, unchanged) ----------------
__global__ __launch_bounds__(256, 2)
void k_proj_mma(int layer,
                const float* __restrict__ b1,
                const float* __restrict__ b2) {
    extern __shared__ char psm[];
    const uint32_t sb = smem_u32(psm);
    const int tid  = threadIdx.x;
    const int wid  = tid >> 5;
    const int lane = tid & 31;
    const int bm   = blockIdx.x;
    const int bn   = blockIdx.y;

    const int wm = (wid >> 1) * 32;
    const int wn = (wid & 1) * 64;

    const __nv_bfloat16* Wh_ = g_wh + (size_t)layer * NH * NH;
    const __nv_bfloat16* Wl_ = g_wl + (size_t)layer * NH * NH;

    const __nv_bfloat16* srcA_h = g_yh + (size_t)bm * 128 * NH;
    const __nv_bfloat16* srcA_l = g_yl + (size_t)bm * 128 * NH;
    const __nv_bfloat16* srcB_h = Wh_ + (size_t)bn * 128 * NH;
    const __nv_bfloat16* srcB_l = Wl_ + (size_t)bn * 128 * NH;

    float* sbias = (float*)(psm + OFF_PBIAS);
    if (tid < 128)
        sbias[tid] = b1[bn * 128 + tid] + b2[bn * 128 + tid];

    const int srow0 = (tid * 2) >> 2,     ssl0 = (tid * 2) & 3;
    const int srow1 = (tid * 2 + 1) >> 2, ssl1 = (tid * 2 + 1) & 3;

    #define PSTAGE(c, bsel)                                                   \
    {                                                                         \
        int kc = (c) * 32;                                                    \
        const __nv_bfloat16* gs[4] = {srcA_h, srcA_l, srcB_h, srcB_l};        \
        _Pragma("unroll")                                                     \
        for (int op = 0; op < 4; op++) {                                      \
            uint32_t base = sb + (uint32_t)(op * 2 + (bsel)) * POPB;          \
            cpasync16(base + srow0 * PROWB + ssl0 * 16,                       \
                      gs[op] + (size_t)srow0 * NH + kc + ssl0 * 8);           \
            cpasync16(base + srow1 * PROWB + ssl1 * 16,                       \
                      gs[op] + (size_t)srow1 * NH + kc + ssl1 * 8);           \
        }                                                                     \
    }

    float acc[2][8][4];
    #pragma unroll
    for (int mt = 0; mt < 2; mt++)
        #pragma unroll
        for (int nt = 0; nt < 8; nt++)
            #pragma unroll
            for (int i = 0; i < 4; i++) acc[mt][nt][i] = 0.0f;

    const int laneRowA = lane & 15;
    const int laneColA = (lane >> 4) * 8;
    const int laneRowB = (lane & 7) + ((lane >> 4) * 8);
    const int laneColB = ((lane >> 3) & 1) * 8;

    PSTAGE(0, 0);
    asm volatile("cp.async.commit_group;");
    asm volatile("cp.async.wait_group 0;");
    __syncthreads();

    #pragma unroll 1
    for (int c = 0; c < 8; c++) {
        int sel = c & 1;
        if (c < 7) {
            PSTAGE(c + 1, sel ^ 1);
            asm volatile("cp.async.commit_group;");
        }
        uint32_t aH = sb + (uint32_t)(0 * 2 + sel) * POPB;
        uint32_t aL = sb + (uint32_t)(1 * 2 + sel) * POPB;
        uint32_t bH = sb + (uint32_t)(2 * 2 + sel) * POPB;
        uint32_t bL = sb + (uint32_t)(3 * 2 + sel) * POPB;

        #pragma unroll
        for (int kk = 0; kk < 32; kk += 16) {
            uint32_t ah[2][4], bb[4][4], al[2][4];
            #pragma unroll
            for (int mt = 0; mt < 2; mt++)
                ldm_x4(ah[mt], aH + (wm + mt * 16 + laneRowA) * PROWB
                               + (kk + laneColA) * 2);
            #pragma unroll
            for (int nb = 0; nb < 4; nb++)
                ldm_x4(bb[nb], bH + (wn + nb * 16 + laneRowB) * PROWB
                               + (kk + laneColB) * 2);
            #pragma unroll
            for (int mt = 0; mt < 2; mt++)
                #pragma unroll
                for (int nt = 0; nt < 8; nt++)
                    mma16816(acc[mt][nt], ah[mt], &bb[nt >> 1][(nt & 1) * 2]);
            #pragma unroll
            for (int mt = 0; mt < 2; mt++)
                ldm_x4(al[mt], aL + (wm + mt * 16 + laneRowA) * PROWB
                               + (kk + laneColA) * 2);
            #pragma unroll
            for (int mt = 0; mt < 2; mt++)
                #pragma unroll
                for (int nt = 0; nt < 8; nt++)
                    mma16816(acc[mt][nt], al[mt], &bb[nt >> 1][(nt & 1) * 2]);
            #pragma unroll
            for (int nb = 0; nb < 4; nb++)
                ldm_x4(bb[nb], bL + (wn + nb * 16 + laneRowB) * PROWB
                               + (kk + laneColB) * 2);
            #pragma unroll
            for (int mt = 0; mt < 2; mt++)
                #pragma unroll
                for (int nt = 0; nt < 8; nt++)
                    mma16816(acc[mt][nt], ah[mt], &bb[nt >> 1][(nt & 1) * 2]);
        }
        if (c < 7) asm volatile("cp.async.wait_group 0;");
        __syncthreads();
    }

    const int rl = lane >> 2;
    const int cl = 2 * (lane & 3);
    #pragma unroll
    for (int mt = 0; mt < 2; mt++) {
        #pragma unroll
        for (int nt = 0; nt < 8; nt++) {
            int gr = bm * 128 + wm + mt * 16 + rl;
            int lc = wn + nt * 8 + cl;
            int gc = bn * 128 + lc;
            float bx = sbias[lc], by = sbias[lc + 1];
            float2 o0 = make_float2(acc[mt][nt][0] + bx, acc[mt][nt][1] + by);
            float2 o1 = make_float2(acc[mt][nt][2] + bx, acc[mt][nt][3] + by);
            *(float2*)(g_xp + (size_t)gr * NH + gc) = o0;
            *(float2*)(g_xp + (size_t)(gr + 8) * NH + gc) = o1;
        }
    }
    #undef PSTAGE
}

// ---------------- final FC ----------------
__global__ void k_fc(const float* __restrict__ Wfc,
                     const float* __restrict__ bfc,
                     float* __restrict__ out) {
    int b = blockIdx.x, lane = threadIdx.x;
    const float* hrow = g_y + ((size_t)b * NT + (NT - 1)) * NH;
    float hv[8];
    #pragma unroll
    for (int k = 0; k < 8; k++) hv[k] = hrow[lane + 32 * k];
    #pragma unroll
    for (int c = 0; c < NC; c++) {
        float s = 0.0f;
        #pragma unroll
        for (int k = 0; k < 8; k++) s += hv[k] * Wfc[c * NH + lane + 32 * k];
        #pragma unroll
        for (int off = 16; off > 0; off >>= 1)
            s += __shfl_xor_sync(0xffffffffu, s, off);
        if (lane == 0) out[b * NC + c] = s + bfc[c];
    }
}

extern "C" void kernel_launch(void* const* d_in, const int* in_sizes, int n_in,
                              void* d_out, int out_size) {
    const float* x    = (const float*)d_in[0];
    const float* W0   = (const float*)d_in[1];
    const float* bi0  = (const float*)d_in[2];
    const float* Wih  = (const float*)d_in[3];
    const float* bih  = (const float*)d_in[4];
    const float* Whh  = (const float*)d_in[5];
    const float* bhh  = (const float*)d_in[6];
    const float* Wfc  = (const float*)d_in[7];
    const float* bfc  = (const float*)d_in[8];
    float* out = (float*)d_out;

    cudaFuncSetAttribute(k_scan, cudaFuncAttributeMaxDynamicSharedMemorySize,
                         SMEM_SCAN_BYTES);
    cudaFuncSetAttribute(k_proj_mma,
                         cudaFuncAttributeMaxDynamicSharedMemorySize,
                         SMEM_PROJ_BYTES);

    k_prep<<<(NL - 1) * NH * NH / 256, 256>>>(Wih);
    k_proj0<<<NB * NT, 256>>>(x, W0, bi0, bhh);
    dim3 pg(NT, 2);
    for (int l = 0; l < NL; l++) {
        k_scan<<<NB, 256, SMEM_SCAN_BYTES>>>(Whh + (size_t)l * NH * NH);
        if (l + 1 < NL)
            k_proj_mma<<<pg, 256, SMEM_PROJ_BYTES>>>(
                l,
                bih + (size_t)l * NH,
                bhh + (size_t)(l + 1) * NH);
    }
    k_fc<<<NB, 32>>>(Wfc, bfc, out);
}